// round 12
// baseline (speedup 1.0000x reference)
#include <cuda_runtime.h>
#include <math.h>

#define Bn 64
#define Tn 1024
#define Kn 128
#define NT 256
#define TAG_START 126
#define TAG_STOP  127
#define NEGV -10000.0f
#define LOG2E 1.4426950408889634f
#define LN2   0.6931471805599453f

__device__ float g_partial[Bn];
__device__ unsigned int g_count = 0;

#define FMA2(acc, x, y) \
    asm("fma.rn.f32x2 %0, %1, %2, %0;" : "+l"(acc) : "l"(x), "l"(y))

#define ADD2(dst, x, y) \
    asm("add.rn.f32x2 %0, %1, %2;" : "=l"(dst) : "l"(x), "l"(y))

#define PACK2(dst, lo, hi) \
    asm("mov.b64 %0, {%1, %2};" : "=l"(dst) : "f"(lo), "f"(hi))

#define UNPACK2(lo, hi, src) \
    asm("mov.b64 {%0, %1}, %2;" : "=f"(lo), "=f"(hi) : "l"(src))

// per-half named barrier: half 0 -> id 1, half 1 -> id 2, 128 threads each
#define BARH() asm volatile("bar.sync %0, 128;" :: "r"(half + 1) : "memory")

__device__ __forceinline__ float ex2(float x) {
    float r; asm("ex2.approx.f32 %0, %1;" : "=f"(r) : "f"(x)); return r;
}
__device__ __forceinline__ float lg2(float x) {
    float r; asm("lg2.approx.f32 %0, %1;" : "=f"(r) : "f"(x)); return r;
}

__global__ __launch_bounds__(NT, 1) void crf_fwd_kernel(
    const float* __restrict__ feats,
    const int*   __restrict__ tags,
    const int*   __restrict__ lens,
    const float* __restrict__ trans,
    float*       __restrict__ out)
{
    const int tid  = threadIdx.x;
    const int half = tid >> 7;          // 0: batch 2B, 1: batch 2B+1
    const int j    = tid & 127;         // tag index, 0..127
    const int b    = blockIdx.x * 2 + half;

    const float* fb = feats + (size_t)b * Tn * Kn;
    const int*   tb = tags + b * Tn;
    const int    len = lens[b];

    __shared__ __align__(16) float eAs[2][2][Kn];   // [half][buf][tag]
    __shared__ float sv0[2][2];                     // [half][buf]
    __shared__ float red[2][Kn];                    // [half][...]
    __shared__ float sh_gold[2];
    __shared__ int   sh_last[2];

    // ---------------- gold score (parallel over t, natural log) ----------------
    float gsum = 0.f;
    for (int t = j; t < Tn; t += Kn) {
        if (t < len)     gsum += fb[t * Kn + tb[t]];
        if (t < len - 1) gsum += trans[tb[t + 1] * Kn + tb[t]];
    }
    red[half][j] = gsum;
    BARH();
    #pragma unroll
    for (int s = 64; s > 0; s >>= 1) {
        if (j < s) red[half][j] += red[half][j + s];
        BARH();
    }
    if (j == 0) sh_gold[half] = red[half][0];

    // ---------------- precompute exp(trans) row j into registers ----------------
    unsigned long long eT2[64];
    #pragma unroll
    for (int i = 0; i < 64; i++) {
        float e0 = ex2(trans[j * Kn + 2 * i]     * LOG2E);
        float e1 = ex2(trans[j * Kn + 2 * i + 1] * LOG2E);
        PACK2(eT2[i], e0, e1);
    }

    // ---------------- init (t = 0), linear domain ----------------
    float f0s = fb[TAG_START];
    float c2f = f0s * LOG2E;            // fractional exponent offset
    int   c2i = 0;                      // integer part (exact, uniform on all lanes)
    eAs[half][0][j] = (j == TAG_START) ? 1.f : 0.f;
    if (j == 0) sv0[half][0] = 1.f;

    // depth-3 feat prefetch
    float fA = (1 < len) ? fb[1 * Kn + j] : 0.f;
    float pA = (2 < len) ? fb[2 * Kn + j] : 0.f;
    float pB = (3 < len) ? fb[3 * Kn + j] : 0.f;
    float ef = ex2(fA * LOG2E);

    // ---------------- sequential forward recursion (1 named barrier/step) --------
    for (int t = 1; t < len; t++) {
        const int cur = (t - 1) & 1;
        const int nxt = t & 1;

        float pC = (t + 3 < len) ? fb[(t + 3) * Kn + j] : 0.f;
        float ef_next = ex2(pA * LOG2E);        // hidden under this step's GEMV

        BARH();                                 // publishes eAs[half][cur], sv0
        float sc = sv0[half][cur];
        float efs = ef * sc;

        const ulonglong2* __restrict__ pV = (const ulonglong2*)eAs[half][cur];
        unsigned long long acc0 = 0ull, acc1 = 0ull, acc2 = 0ull, acc3 = 0ull;
        #pragma unroll
        for (int i = 0; i < 32; i++) {
            ulonglong2 p = pV[i];               // LDS.128 broadcast
            if ((i & 1) == 0) {
                FMA2(acc0, p.x, eT2[2 * i]);
                FMA2(acc1, p.y, eT2[2 * i + 1]);
            } else {
                FMA2(acc2, p.x, eT2[2 * i]);
                FMA2(acc3, p.y, eT2[2 * i + 1]);
            }
        }
        unsigned long long s01, s23, sall;
        ADD2(s01, acc0, acc1);
        ADD2(s23, acc2, acc3);
        ADD2(sall, s01, s23);
        float lo, hi;
        UNPACK2(lo, hi, sall);
        float dot = lo + hi;

        float w = dot * efs;
        eAs[half][nxt][j] = w;
        if (j == 0) {                    // j==0 owns w[0]: publish next scale only
            int e = (__float_as_int(w) >> 23) - 127;       // w > 0, normal
            sv0[half][nxt] = __int_as_float((127 - e) << 23);  // 2^-e exactly
        }
        c2i += 127 - (__float_as_int(sc) >> 23);   // uniform ALU, off-chain

        ef = ef_next; fA = pA; pA = pB; pB = pC;
    }

    // ---------------- terminal: log2(sum w) + exponent offset ----------------
    BARH();
    red[half][j] = eAs[half][(len - 1) & 1][j];
    BARH();
    #pragma unroll
    for (int s = 64; s > 0; s >>= 1) {
        if (j < s) red[half][j] += red[half][j + s];
        BARH();
    }
    if (j == 0) {
        float forward = ((float)c2i + c2f + lg2(red[half][0])) * LN2;
        g_partial[b] = forward - sh_gold[half];
        __threadfence();
        unsigned int f = atomicAdd(&g_count, 1);
        sh_last[half] = (f == Bn - 1);
    }
    BARH();

    // last half (of all 64) to finish reduces the mean with its 128 threads
    if (sh_last[half]) {
        __threadfence();
        red[half][j] = (j < Bn) ? g_partial[j] : 0.f;
        BARH();
        #pragma unroll
        for (int s = 64; s > 0; s >>= 1) {
            if (j < s) red[half][j] += red[half][j + s];
            BARH();
        }
        if (j == 0) {
            out[0] = red[half][0] * (1.0f / Bn);
            g_count = 0;                 // reset for graph replay
        }
    }
}

extern "C" void kernel_launch(void* const* d_in, const int* in_sizes, int n_in,
                              void* d_out, int out_size)
{
    const float* feats = (const float*)d_in[0];
    const int*   tags  = (const int*)d_in[1];
    const int*   lens  = (const int*)d_in[2];
    const float* trans = (const float*)d_in[3];
    float* out = (float*)d_out;

    crf_fwd_kernel<<<Bn / 2, NT>>>(feats, tags, lens, trans, out);
}

// round 14
// speedup vs baseline: 1.4722x; 1.4722x over previous
#include <cuda_runtime.h>
#include <math.h>

#define Bn 64
#define Tn 1024
#define Kn 128
#define TAG_START 126
#define TAG_STOP  127
#define NEGV -10000.0f
#define LOG2E 1.4426950408889634f
#define LN2   0.6931471805599453f

__device__ float g_partial[Bn];
__device__ unsigned int g_count = 0;

#define FMA2(acc, x, y) \
    asm("fma.rn.f32x2 %0, %1, %2, %0;" : "+l"(acc) : "l"(x), "l"(y))

#define ADD2(dst, x, y) \
    asm("add.rn.f32x2 %0, %1, %2;" : "=l"(dst) : "l"(x), "l"(y))

#define PACK2(dst, lo, hi) \
    asm("mov.b64 %0, {%1, %2};" : "=l"(dst) : "f"(lo), "f"(hi))

#define UNPACK2(lo, hi, src) \
    asm("mov.b64 {%0, %1}, %2;" : "=f"(lo), "=f"(hi) : "l"(src))

__device__ __forceinline__ float ex2(float x) {
    float r; asm("ex2.approx.f32 %0, %1;" : "=f"(r) : "f"(x)); return r;
}
__device__ __forceinline__ float lg2(float x) {
    float r; asm("lg2.approx.f32 %0, %1;" : "=f"(r) : "f"(x)); return r;
}

// One forward step; CUR/NXT are compile-time buffer indices in the unrolled body.
#define FWD_STEP(T, CUR, NXT) do {                                            \
    float pC = ((T) + 3 < len) ? fb[((T) + 3) * Kn + j] : 0.f;                \
    float ef_next = ex2(pA * LOG2E);     /* hidden under this step's GEMV */  \
    __syncthreads();                     /* publishes eAs[CUR], sv0[CUR] */   \
    float sc = sv0[CUR];                 /* lagged power-of-2 scale */        \
    float efs = ef * sc;                 /* off the critical chain */         \
    const ulonglong2* __restrict__ pV = (const ulonglong2*)eAs[CUR];          \
    unsigned long long acc0 = 0ull, acc1 = 0ull, acc2 = 0ull, acc3 = 0ull;    \
    _Pragma("unroll")                                                         \
    for (int i = 0; i < 32; i++) {                                            \
        ulonglong2 p = pV[i];            /* LDS.128 broadcast */              \
        if ((i & 1) == 0) {                                                   \
            FMA2(acc0, p.x, eT2[2 * i]);                                      \
            FMA2(acc1, p.y, eT2[2 * i + 1]);                                  \
        } else {                                                              \
            FMA2(acc2, p.x, eT2[2 * i]);                                      \
            FMA2(acc3, p.y, eT2[2 * i + 1]);                                  \
        }                                                                     \
    }                                                                         \
    unsigned long long s01, s23, sall;                                        \
    ADD2(s01, acc0, acc1);                                                    \
    ADD2(s23, acc2, acc3);                                                    \
    ADD2(sall, s01, s23);                                                     \
    float lo, hi;                                                             \
    UNPACK2(lo, hi, sall);                                                    \
    float dot = lo + hi;                                                      \
    float wv = dot * efs;                /* single FMUL after the dot */      \
    eAs[NXT][j] = wv;                                                         \
    if (j == 0) {                        /* j==0 owns w[0]: publish scale */  \
        int e = (__float_as_int(wv) >> 23) - 127;       /* w > 0, normal */   \
        sv0[NXT] = __int_as_float((127 - e) << 23);     /* 2^-e exactly */    \
    }                                                                         \
    c2i += 127 - (__float_as_int(sc) >> 23);  /* uniform ALU, off-chain */    \
    ef = ef_next; fA = pA; pA = pB; pB = pC;                                  \
} while (0)

__global__ __launch_bounds__(128, 1) void crf_fwd_kernel(
    const float* __restrict__ feats,
    const int*   __restrict__ tags,
    const int*   __restrict__ lens,
    const float* __restrict__ trans,
    float*       __restrict__ out)
{
    const int b = blockIdx.x;
    const int j = threadIdx.x;          // tag index, 0..127
    const float* fb = feats + (size_t)b * Tn * Kn;
    const int*   tb = tags + b * Tn;
    const int    len = lens[b];

    __shared__ __align__(16) float eAs[2][Kn];
    __shared__ float sv0[2];            // lagged power-of-2 scale
    __shared__ float red[Kn];
    __shared__ float sh_gold;
    __shared__ int   sh_last;

    // ---------------- gold score (parallel over t, natural log) ----------------
    float gsum = 0.f;
    for (int t = j; t < Tn; t += Kn) {
        if (t < len)     gsum += fb[t * Kn + tb[t]];
        if (t < len - 1) gsum += trans[tb[t + 1] * Kn + tb[t]];
    }
    red[j] = gsum;
    __syncthreads();
    #pragma unroll
    for (int s = 64; s > 0; s >>= 1) {
        if (j < s) red[j] += red[j + s];
        __syncthreads();
    }
    if (j == 0) sh_gold = red[0];

    // ---------------- precompute exp(trans) row j into registers ----------------
    unsigned long long eT2[64];
    #pragma unroll
    for (int i = 0; i < 64; i++) {
        float e0 = ex2(trans[j * Kn + 2 * i]     * LOG2E);
        float e1 = ex2(trans[j * Kn + 2 * i + 1] * LOG2E);
        PACK2(eT2[i], e0, e1);
    }

    // ---------------- init (t = 0), linear domain ----------------
    float f0s = fb[TAG_START];
    float c2f = f0s * LOG2E;            // fractional exponent offset
    int   c2i = 0;                      // integer part (exact, uniform on all lanes)
    eAs[0][j] = (j == TAG_START) ? 1.f : 0.f;
    if (j == 0) sv0[0] = 1.f;

    // depth-3 feat prefetch
    float fA = (1 < len) ? fb[1 * Kn + j] : 0.f;
    float pA = (2 < len) ? fb[2 * Kn + j] : 0.f;
    float pB = (3 < len) ? fb[3 * Kn + j] : 0.f;
    float ef = ex2(fA * LOG2E);         // exp(feat[1][j])

    // ---------------- sequential forward recursion, unrolled by 2 ----------------
    int t = 1;
    for (; t + 1 < len; t += 2) {
        FWD_STEP(t,     0, 1);
        FWD_STEP(t + 1, 1, 0);
    }
    if (t < len) {
        FWD_STEP(t, 0, 1);              // odd tail: t is odd => cur=0, nxt=1
    }

    // ---------------- terminal: log2(sum w) + exponent offset ----------------
    __syncthreads();
    float wfin = eAs[(len - 1) & 1][j];
    red[j] = wfin;
    __syncthreads();
    #pragma unroll
    for (int s = 64; s > 0; s >>= 1) {
        if (j < s) red[j] += red[j + s];
        __syncthreads();
    }
    if (j == 0) {
        float forward = ((float)c2i + c2f + lg2(red[0])) * LN2;
        g_partial[b] = forward - sh_gold;
        __threadfence();
        unsigned int f = atomicAdd(&g_count, 1);
        sh_last = (f == Bn - 1);
    }
    __syncthreads();

    // last block to finish reduces the mean
    if (sh_last) {
        __threadfence();
        red[j] = (j < Bn) ? g_partial[j] : 0.f;
        __syncthreads();
        #pragma unroll
        for (int s = 32; s > 0; s >>= 1) {
            if (j < s) red[j] += red[j + s];
            __syncthreads();
        }
        if (j == 0) {
            out[0] = red[0] * (1.0f / Bn);
            g_count = 0;                 // reset for graph replay
        }
    }
}

extern "C" void kernel_launch(void* const* d_in, const int* in_sizes, int n_in,
                              void* d_out, int out_size)
{
    const float* feats = (const float*)d_in[0];
    const int*   tags  = (const int*)d_in[1];
    const int*   lens  = (const int*)d_in[2];
    const float* trans = (const float*)d_in[3];
    float* out = (float*)d_out;

    crf_fwd_kernel<<<Bn, Kn>>>(feats, tags, lens, trans, out);
}